// round 6
// baseline (speedup 1.0000x reference)
#include <cuda_runtime.h>
#include <cuda_fp16.h>
#include <cstdint>

#define NB 64
#define S  512
#define NEG_MASK -999999.0f

#define TENS ((size_t)NB * S * S)

// ---------------- scratch ---------------------------------------------------
__device__ float  g_sim[TENS];
__device__ __half g_buf[8 * TENS];

#define PRE_HI  0
#define PRE_LO  1
#define PRE_THI 2
#define HYP_HI  3
#define HYP_LO  4
#define HYP_THI 5
#define ATT_AHI 6
#define ATT_BHI 7

// ---------------- helpers ---------------------------------------------------
__device__ __forceinline__ uint32_t smem_to_u32(const void* p) {
    uint32_t a;
    asm("{ .reg .u64 t; cvta.to.shared.u64 t, %1; cvt.u32.u64 %0, t; }" : "=r"(a) : "l"(p));
    return a;
}
__device__ __forceinline__ void ldsm_x4(uint32_t* r, uint32_t addr) {
    asm volatile("ldmatrix.sync.aligned.m8n8.x4.shared.b16 {%0,%1,%2,%3}, [%4];"
                 : "=r"(r[0]), "=r"(r[1]), "=r"(r[2]), "=r"(r[3]) : "r"(addr));
}
__device__ __forceinline__ void ldsm_x2(uint32_t* r, uint32_t addr) {
    asm volatile("ldmatrix.sync.aligned.m8n8.x2.shared.b16 {%0,%1}, [%2];"
                 : "=r"(r[0]), "=r"(r[1]) : "r"(addr));
}
__device__ __forceinline__ void mma16816(float* c, const uint32_t* a, const uint32_t* b) {
    asm volatile(
        "mma.sync.aligned.m16n8k16.row.col.f32.f16.f16.f32 "
        "{%0,%1,%2,%3}, {%4,%5,%6,%7}, {%8,%9}, {%0,%1,%2,%3};"
        : "+f"(c[0]), "+f"(c[1]), "+f"(c[2]), "+f"(c[3])
        : "r"(a[0]), "r"(a[1]), "r"(a[2]), "r"(a[3]), "r"(b[0]), "r"(b[1]));
}

// ---------------------------------------------------------------------------
// Conversion (both inputs in one launch): fp32 X -> hi/lo fp16 + hi transposed
// grid (16,16,2*NB), block (32,8); z<NB: tensor 1, else tensor 2
// ---------------------------------------------------------------------------
__global__ __launch_bounds__(256)
void convert_split_kernel(const float* __restrict__ X1,
                          __half* __restrict__ hi1, __half* __restrict__ lo1,
                          __half* __restrict__ thi1,
                          const float* __restrict__ X2,
                          __half* __restrict__ hi2, __half* __restrict__ lo2,
                          __half* __restrict__ thi2)
{
    __shared__ __half sh[32][33];
    const int tx = threadIdx.x, ty = threadIdx.y;
    const int zb = blockIdx.z;
    const float* X;
    __half *hi, *lo, *thi;
    if (zb < NB) { X = X1; hi = hi1; lo = lo1; thi = thi1; }
    else         { X = X2; hi = hi2; lo = lo2; thi = thi2; }
    const size_t base = (size_t)(zb & (NB - 1)) * S * S;
    const int r0 = blockIdx.y * 32, c0 = blockIdx.x * 32;
#pragma unroll
    for (int j = 0; j < 4; j++) {
        int rl = ty + j * 8;
        size_t idx = base + (size_t)(r0 + rl) * S + c0 + tx;
        float x = X[idx];
        __half h = __float2half_rn(x);
        hi[idx] = h;
        lo[idx] = __float2half_rn(x - __half2float(h));
        sh[rl][tx] = h;
    }
    __syncthreads();
#pragma unroll
    for (int j = 0; j < 4; j++) {
        int cl = ty + j * 8;
        thi[base + (size_t)(c0 + cl) * S + r0 + tx] = sh[tx][cl];
    }
}

// ---------------------------------------------------------------------------
// fp16 tensor-core GEMM (mma.sync m16n8k16), K-major A and B, fp32 out.
// NTERMS=3: C = Ahi*Bhi + Ahi*Blo + Alo*Bhi  (sim GEMM, 3 stages, 96 KB)
// NTERMS=1: C = A*B                          (attended GEMMs, 4 stages, 64 KB)
// 128x128 CTA tile, BK=32, single __syncthreads per K-iter (multistage).
// ---------------------------------------------------------------------------
template<int NTERMS>
__global__ __launch_bounds__(256, 2)
void gemm_tc_kernel(const __half* __restrict__ Ahi, const __half* __restrict__ Alo,
                    const __half* __restrict__ Bhi, const __half* __restrict__ Blo,
                    float* __restrict__ C,
                    const __half* __restrict__ A2, const __half* __restrict__ B2,
                    float* __restrict__ C2)
{
    constexpr int NTILES  = (NTERMS == 3) ? 4 : 2;
    constexpr int NSTAGES = (NTERMS == 3) ? 3 : 4;
    constexpr int TSZ     = 8192;
    constexpr int STSZ    = NTILES * TSZ;
    constexpr int BOFFS   = (NTERMS == 3) ? 2 * TSZ : TSZ;
    constexpr int NITER   = 16;

    extern __shared__ char smem[];
    const uint32_t sb = smem_to_u32(smem);
    const int tid = threadIdx.x;
    const int lane = tid & 31, wid = tid >> 5;
    const int wm = wid >> 2;            // 0..1
    const int wn = wid & 3;             // 0..3
    const int zb = blockIdx.z;
    const size_t boff = (size_t)(zb & (NB - 1)) * S * S;
    const int m0 = blockIdx.y * 128, n0 = blockIdx.x * 128;

    const __half* gsrc[NTILES];
    float* Cout;
    if (NTERMS == 3) {
        gsrc[0] = Ahi + boff + (size_t)m0 * S;
        gsrc[1] = Alo + boff + (size_t)m0 * S;
        gsrc[2] = Bhi + boff + (size_t)n0 * S;
        gsrc[NTILES - 1] = Blo + boff + (size_t)n0 * S;
        Cout = C;
    } else {
        // z<NB: (Ahi,Bhi)->C ; z>=NB: (A2,B2)->C2
        if (zb < NB) {
            gsrc[0] = Ahi + boff + (size_t)m0 * S;
            gsrc[NTILES - 1] = Bhi + boff + (size_t)n0 * S;
            Cout = C;
        } else {
            gsrc[0] = A2 + boff + (size_t)m0 * S;
            gsrc[NTILES - 1] = B2 + boff + (size_t)n0 * S;
            Cout = C2;
        }
    }

    auto load_stage = [&](int st, int k0) {
        uint32_t base = sb + st * STSZ;
#pragma unroll
        for (int t = 0; t < NTILES; t++) {
            const __half* g = gsrc[t] + k0;
            uint32_t tb = base + t * TSZ;
#pragma unroll
            for (int j = 0; j < 2; j++) {
                int idx = j * 256 + tid;                 // 0..511 16B chunks
                int row = idx >> 2, c = idx & 3;
                uint32_t dst = tb + row * 64 + ((uint32_t)(c ^ ((row >> 1) & 3)) << 4);
                const void* src = g + row * S + c * 8;
                asm volatile("cp.async.cg.shared.global [%0], [%1], 16;"
                             :: "r"(dst), "l"(src) : "memory");
            }
        }
        asm volatile("cp.async.commit_group;" ::: "memory");
    };

    float acc[4][4][4];
#pragma unroll
    for (int i = 0; i < 4; i++)
#pragma unroll
        for (int j = 0; j < 4; j++)
#pragma unroll
            for (int q = 0; q < 4; q++) acc[i][j][q] = 0.0f;

    // prologue: stages 0..NSTAGES-2
#pragma unroll
    for (int s = 0; s < NSTAGES - 1; s++) load_stage(s, s * 32);

    for (int i = 0; i < NITER; i++) {
        if (NSTAGES == 4) asm volatile("cp.async.wait_group 2;" ::: "memory");
        else              asm volatile("cp.async.wait_group 1;" ::: "memory");
        __syncthreads();   // stage i visible to all; compute(i-1) done -> stage free
        if (i + NSTAGES - 1 < NITER)
            load_stage((i + NSTAGES - 1) % NSTAGES, (i + NSTAGES - 1) * 32);
        else
            asm volatile("cp.async.commit_group;" ::: "memory");

        const uint32_t stb = sb + (i % NSTAGES) * STSZ;
#pragma unroll
        for (int ks = 0; ks < 2; ks++) {
            uint32_t ah[4][4], al[4][4];
#pragma unroll
            for (int mf = 0; mf < 4; mf++) {
                int row = wm * 64 + mf * 16 + (lane & 15);
                int ch = (ks * 2 + (lane >> 4)) ^ ((row >> 1) & 3);
                uint32_t off = row * 64 + (ch << 4);
                ldsm_x4(ah[mf], stb + off);
                if (NTERMS == 3) ldsm_x4(al[mf], stb + TSZ + off);
            }
#pragma unroll
            for (int nf = 0; nf < 4; nf++) {
                int row = wn * 32 + nf * 8 + (lane & 7);
                int ch = (ks * 2 + ((lane >> 3) & 1)) ^ ((row >> 1) & 3);
                uint32_t off = row * 64 + (ch << 4);
                uint32_t bh[2], bl[2];
                ldsm_x2(bh, stb + BOFFS + off);
                if (NTERMS == 3) ldsm_x2(bl, stb + BOFFS + TSZ + off);
#pragma unroll
                for (int mf = 0; mf < 4; mf++) {
                    mma16816(acc[mf][nf], ah[mf], bh);
                    if (NTERMS == 3) {
                        mma16816(acc[mf][nf], ah[mf], bl);
                        mma16816(acc[mf][nf], al[mf], bh);
                    }
                }
            }
        }
    }

    float* Cb = Cout + boff;
#pragma unroll
    for (int mf = 0; mf < 4; mf++) {
#pragma unroll
        for (int nf = 0; nf < 4; nf++) {
            int r  = m0 + wm * 64 + mf * 16 + (lane >> 2);
            int cc = n0 + wn * 32 + nf * 8 + (lane & 3) * 2;
            *(float2*)&Cb[(size_t)r * S + cc]       = make_float2(acc[mf][nf][0], acc[mf][nf][1]);
            *(float2*)&Cb[(size_t)(r + 8) * S + cc] = make_float2(acc[mf][nf][2], acc[mf][nf][3]);
        }
    }
}

// ---------------------------------------------------------------------------
// Row softmax (attention_a): one warp per row, shfl reductions -> fp16.
// grid (S/8, NB), block 256
// ---------------------------------------------------------------------------
__global__ __launch_bounds__(256)
void softmax_row_kernel(const int* __restrict__ pre_mask,
                        __half* __restrict__ ahi)
{
    const int b = blockIdx.y;
    const int w = threadIdx.x >> 5, lane = threadIdx.x & 31;
    const int p = blockIdx.x * 8 + w;
    const float c = (pre_mask[b * S + p] == 0) ? NEG_MASK : 0.0f;
    const size_t off = ((size_t)b * S + p) * S;
    const float* row = g_sim + off;

    float4 v[4];
#pragma unroll
    for (int seg = 0; seg < 4; seg++) {
        v[seg] = *(const float4*)&row[seg * 128 + lane * 4];
        v[seg].x += c; v[seg].y += c; v[seg].z += c; v[seg].w += c;
    }

    float M = -3.0e38f;
#pragma unroll
    for (int seg = 0; seg < 4; seg++)
        M = fmaxf(M, fmaxf(fmaxf(v[seg].x, v[seg].y), fmaxf(v[seg].z, v[seg].w)));
#pragma unroll
    for (int o = 16; o > 0; o >>= 1)
        M = fmaxf(M, __shfl_xor_sync(0xFFFFFFFFu, M, o));

    float s = 0.0f;
    float4 e[4];
#pragma unroll
    for (int seg = 0; seg < 4; seg++) {
        e[seg].x = __expf(v[seg].x - M); e[seg].y = __expf(v[seg].y - M);
        e[seg].z = __expf(v[seg].z - M); e[seg].w = __expf(v[seg].w - M);
        s += e[seg].x + e[seg].y + e[seg].z + e[seg].w;
    }
#pragma unroll
    for (int o = 16; o > 0; o >>= 1)
        s += __shfl_xor_sync(0xFFFFFFFFu, s, o);
    const float inv = 1.0f / s;

#pragma unroll
    for (int seg = 0; seg < 4; seg++) {
        size_t o4 = off + seg * 128 + lane * 4;
        *(__half2*)&ahi[o4]     = __halves2half2(__float2half_rn(e[seg].x * inv),
                                                 __float2half_rn(e[seg].y * inv));
        *(__half2*)&ahi[o4 + 2] = __halves2half2(__float2half_rn(e[seg].z * inv),
                                                 __float2half_rn(e[seg].w * inv));
    }
}

// ---------------------------------------------------------------------------
// Column softmax (attention_b) -> fp16 written TRANSPOSED [h][p],
// coalesced via 64x64 smem transpose tiles. grid (S/64, NB), block 256.
// ---------------------------------------------------------------------------
__global__ __launch_bounds__(256)
void softmax_col_kernel(const int* __restrict__ hyp_mask,
                        __half* __restrict__ bhi)
{
    const int b   = blockIdx.y;
    const int h0  = blockIdx.x * 64;
    const int t   = threadIdx.x;
    const int col = t & 63, strip = t >> 6;
    const int h   = h0 + col;
    const float c = (hyp_mask[b * S + h] == 0) ? NEG_MASK : 0.0f;
    const float* simb = g_sim + (size_t)b * S * S;

    // phase 1: online max/sum per column, 4 strips of 128 p
    float m = -3.0e38f, s = 0.0f;
    const int p0s = strip * 128;
    for (int p = p0s; p < p0s + 128; ++p) {
        float v = simb[p * S + h] + c;
        if (v > m) { s = s * __expf(m - v) + 1.0f; m = v; }
        else       { s += __expf(v - m); }
    }

    __shared__ float sm[4][64], ss[4][64], Mf[64], If[64], Cf[64];
    sm[strip][col] = m;
    ss[strip][col] = s;
    if (strip == 0) Cf[col] = c;
    __syncthreads();
    if (strip == 0) {
        float M = -3.0e38f;
#pragma unroll
        for (int i = 0; i < 4; i++) M = fmaxf(M, sm[i][col]);
        float Ssum = 0.0f;
#pragma unroll
        for (int i = 0; i < 4; i++) Ssum += ss[i][col] * __expf(sm[i][col] - M);
        Mf[col] = M;
        If[col] = 1.0f / Ssum;
    }
    __syncthreads();

    // phase 2: compute w, transpose through smem, write [h][p] coalesced
    __shared__ __half thi[64][66];
    const float cc = Cf[col], MM = Mf[col], ii = If[col];
    for (int p0 = 0; p0 < S; p0 += 64) {
#pragma unroll
        for (int j = 0; j < 16; j++) {
            int pi = strip * 16 + j;
            float v = simb[(p0 + pi) * S + h] + cc;
            thi[col][pi] = __float2half_rn(__expf(v - MM) * ii);
        }
        __syncthreads();
#pragma unroll
        for (int j = 0; j < 16; j++) {
            int hy = strip * 16 + j;
            size_t o = (size_t)b * S * S + (size_t)(h0 + hy) * S + p0 + col;
            bhi[o] = thi[hy][col];
        }
        __syncthreads();
    }
}

// ---------------------------------------------------------------------------
extern "C" void kernel_launch(void* const* d_in, const int* in_sizes, int n_in,
                              void* d_out, int out_size)
{
    const float* premise  = (const float*)d_in[0];
    const int*   pre_mask = (const int*)  d_in[1];
    const float* hypo     = (const float*)d_in[2];
    const int*   hyp_mask = (const int*)  d_in[3];
    float* out1 = (float*)d_out;
    float* out2 = out1 + TENS;

    float*  sim;
    __half* buf;
    cudaGetSymbolAddress((void**)&sim, g_sim);
    cudaGetSymbolAddress((void**)&buf, g_buf);
    auto slot = [&](int i) { return buf + (size_t)i * TENS; };

    const int SMEM3 = 3 * 4 * 8192;   // 96 KB
    const int SMEM1 = 4 * 2 * 8192;   // 64 KB
    cudaFuncSetAttribute(gemm_tc_kernel<3>,
                         cudaFuncAttributeMaxDynamicSharedMemorySize, SMEM3);
    cudaFuncSetAttribute(gemm_tc_kernel<1>,
                         cudaFuncAttributeMaxDynamicSharedMemorySize, SMEM1);

    // 1. hi/lo fp16 splits (+hi transposes) of both inputs, one launch
    convert_split_kernel<<<dim3(16, 16, 2 * NB), dim3(32, 8)>>>(
        premise, slot(PRE_HI), slot(PRE_LO), slot(PRE_THI),
        hypo,    slot(HYP_HI), slot(HYP_LO), slot(HYP_THI));

    // 2. sim = premise @ hypothesis^T  (3-term split)
    gemm_tc_kernel<3><<<dim3(4, 4, NB), 256, SMEM3>>>(
        slot(PRE_HI), slot(PRE_LO), slot(HYP_HI), slot(HYP_LO), sim,
        nullptr, nullptr, nullptr);

    // 3. softmaxes -> fp16 attention (attB transposed)
    softmax_row_kernel<<<dim3(S / 8, NB), 256>>>(pre_mask, slot(ATT_AHI));
    softmax_col_kernel<<<dim3(S / 64, NB), 256>>>(hyp_mask, slot(ATT_BHI));

    // 4+5. both attended GEMMs in one launch (z<NB: attA@hyp ; z>=NB: attB^T@pre)
    gemm_tc_kernel<1><<<dim3(4, 4, 2 * NB), 256, SMEM1>>>(
        slot(ATT_AHI), nullptr, slot(HYP_THI), nullptr, out1,
        slot(ATT_BHI), slot(PRE_THI), out2);
}

// round 8
// speedup vs baseline: 1.1097x; 1.1097x over previous
#include <cuda_runtime.h>
#include <cuda_fp16.h>
#include <cstdint>

#define NB 64
#define S  512
#define NEG_MASK -999999.0f

#define TENS ((size_t)NB * S * S)

// ---------------- scratch ---------------------------------------------------
__device__ float  g_sim [TENS];
__device__ float  g_simT[TENS];
__device__ __half g_buf[6 * TENS];

#define PRE_HI  0
#define PRE_LO  1
#define HYP_HI  2
#define HYP_LO  3
#define ATT_A   4
#define ATT_BT  5

// ---------------- helpers ---------------------------------------------------
__device__ __forceinline__ uint32_t smem_to_u32(const void* p) {
    uint32_t a;
    asm("{ .reg .u64 t; cvta.to.shared.u64 t, %1; cvt.u32.u64 %0, t; }" : "=r"(a) : "l"(p));
    return a;
}
__device__ __forceinline__ void ldsm_x4(uint32_t* r, uint32_t addr) {
    asm volatile("ldmatrix.sync.aligned.m8n8.x4.shared.b16 {%0,%1,%2,%3}, [%4];"
                 : "=r"(r[0]), "=r"(r[1]), "=r"(r[2]), "=r"(r[3]) : "r"(addr));
}
__device__ __forceinline__ void ldsm_x2(uint32_t* r, uint32_t addr) {
    asm volatile("ldmatrix.sync.aligned.m8n8.x2.shared.b16 {%0,%1}, [%2];"
                 : "=r"(r[0]), "=r"(r[1]) : "r"(addr));
}
__device__ __forceinline__ void ldsm_x2_trans(uint32_t* r, uint32_t addr) {
    asm volatile("ldmatrix.sync.aligned.m8n8.x2.trans.shared.b16 {%0,%1}, [%2];"
                 : "=r"(r[0]), "=r"(r[1]) : "r"(addr));
}
__device__ __forceinline__ void mma16816(float* c, const uint32_t* a, const uint32_t* b) {
    asm volatile(
        "mma.sync.aligned.m16n8k16.row.col.f32.f16.f16.f32 "
        "{%0,%1,%2,%3}, {%4,%5,%6,%7}, {%8,%9}, {%0,%1,%2,%3};"
        : "+f"(c[0]), "+f"(c[1]), "+f"(c[2]), "+f"(c[3])
        : "r"(a[0]), "r"(a[1]), "r"(a[2]), "r"(a[3]), "r"(b[0]), "r"(b[1]));
}
__device__ __forceinline__ uint32_t pack2(__half a, __half b) {
    __half2 h = __halves2half2(a, b);
    return *reinterpret_cast<uint32_t*>(&h);
}

// ---------------------------------------------------------------------------
// Element-wise hi/lo fp16 split of both inputs. grid (TENS/1024, 2), block 256.
// ---------------------------------------------------------------------------
__global__ __launch_bounds__(256)
void convert_split_kernel(const float4* __restrict__ X1,
                          uint2* __restrict__ hi1, uint2* __restrict__ lo1,
                          const float4* __restrict__ X2,
                          uint2* __restrict__ hi2, uint2* __restrict__ lo2)
{
    const float4* X = blockIdx.y ? X2 : X1;
    uint2* hi = blockIdx.y ? hi2 : hi1;
    uint2* lo = blockIdx.y ? lo2 : lo1;
    size_t i = (size_t)blockIdx.x * 256 + threadIdx.x;
    float4 v = X[i];
    __half h0 = __float2half_rn(v.x), h1 = __float2half_rn(v.y);
    __half h2 = __float2half_rn(v.z), h3 = __float2half_rn(v.w);
    uint2 H, L;
    H.x = pack2(h0, h1);
    H.y = pack2(h2, h3);
    L.x = pack2(__float2half_rn(v.x - __half2float(h0)),
                __float2half_rn(v.y - __half2float(h1)));
    L.y = pack2(__float2half_rn(v.z - __half2float(h2)),
                __float2half_rn(v.w - __half2float(h3)));
    hi[i] = H;
    lo[i] = L;
}

// ---------------------------------------------------------------------------
// fp16 tensor-core GEMM (mma.sync m16n8k16), fp32 out.
// NTERMS=3: C = Ahi*Bhi + Ahi*Blo + Alo*Bhi ; B K-major [n][k]; writes C + CT.
// NTERMS=1: C = A*B ; B row-major [k][n] via ldmatrix.trans; merged dual launch.
// 128x128 CTA tile, BK=32, multistage cp.async, 2 CTAs/SM.
// ---------------------------------------------------------------------------
template<int NTERMS>
__global__ __launch_bounds__(256, 2)
void gemm_tc_kernel(const __half* __restrict__ Ahi, const __half* __restrict__ Alo,
                    const __half* __restrict__ Bhi, const __half* __restrict__ Blo,
                    float* __restrict__ C, float* __restrict__ CT,
                    const __half* __restrict__ A2, const __half* __restrict__ B2,
                    float* __restrict__ C2)
{
    constexpr int NTILES  = (NTERMS == 3) ? 4 : 2;
    constexpr int NSTAGES = (NTERMS == 3) ? 3 : 4;
    constexpr int TSZ     = 8192;
    constexpr int STSZ    = NTILES * TSZ;
    constexpr int NITER   = 16;

    extern __shared__ char smem[];
    const uint32_t sb = smem_to_u32(smem);
    const int tid = threadIdx.x;
    const int lane = tid & 31, wid = tid >> 5;
    const int wm = wid >> 2;            // 0..1
    const int wn = wid & 3;             // 0..3
    const int zb = blockIdx.z;
    const size_t boff = (size_t)(zb & (NB - 1)) * S * S;
    const int m0 = blockIdx.y * 128, n0 = blockIdx.x * 128;

    const __half *gAhi, *gAlo, *gBhi, *gBlo, *gBkn;
    float* Cout;
    if (NTERMS == 3) {
        gAhi = Ahi + boff + (size_t)m0 * S;
        gAlo = Alo + boff + (size_t)m0 * S;
        gBhi = Bhi + boff + (size_t)n0 * S;
        gBlo = Blo + boff + (size_t)n0 * S;
        Cout = C;
    } else {
        if (zb < NB) { gAhi = Ahi + boff + (size_t)m0 * S; gBkn = Bhi + boff + n0; Cout = C; }
        else         { gAhi = A2  + boff + (size_t)m0 * S; gBkn = B2  + boff + n0; Cout = C2; }
    }

    auto load_stage = [&](int st, int k0) {
        uint32_t base = sb + st * STSZ;
        if (NTERMS == 3) {
            const __half* gs[4] = {gAhi, gAlo, gBhi, gBlo};
#pragma unroll
            for (int t = 0; t < 4; t++) {
                const __half* g = gs[t] + k0;
                uint32_t tb = base + t * TSZ;
#pragma unroll
                for (int j = 0; j < 2; j++) {
                    int idx = j * 256 + tid;
                    int row = idx >> 2, c = idx & 3;
                    uint32_t dst = tb + row * 64 + ((uint32_t)(c ^ ((row >> 1) & 3)) << 4);
                    asm volatile("cp.async.cg.shared.global [%0], [%1], 16;"
                                 :: "r"(dst), "l"(g + row * S + c * 8) : "memory");
                }
            }
        } else {
            // A tile [m128][k32], 64B rows
#pragma unroll
            for (int j = 0; j < 2; j++) {
                int idx = j * 256 + tid;
                int row = idx >> 2, c = idx & 3;
                uint32_t dst = base + row * 64 + ((uint32_t)(c ^ ((row >> 1) & 3)) << 4);
                asm volatile("cp.async.cg.shared.global [%0], [%1], 16;"
                             :: "r"(dst), "l"(gAhi + row * S + k0 + c * 8) : "memory");
            }
            // B tile [k32][n128], 256B rows, row-XOR swizzle
#pragma unroll
            for (int j = 0; j < 2; j++) {
                int idx = j * 256 + tid;
                int row = idx >> 4, c = idx & 15;
                uint32_t dst = base + TSZ + row * 256 + ((uint32_t)(c ^ (row & 7)) << 4);
                asm volatile("cp.async.cg.shared.global [%0], [%1], 16;"
                             :: "r"(dst), "l"(gBkn + (size_t)(k0 + row) * S + c * 8) : "memory");
            }
        }
        asm volatile("cp.async.commit_group;" ::: "memory");
    };

    float acc[4][4][4];
#pragma unroll
    for (int i = 0; i < 4; i++)
#pragma unroll
        for (int j = 0; j < 4; j++)
#pragma unroll
            for (int q = 0; q < 4; q++) acc[i][j][q] = 0.0f;

#pragma unroll
    for (int s = 0; s < NSTAGES - 1; s++) load_stage(s, s * 32);

    for (int i = 0; i < NITER; i++) {
        if (NSTAGES == 4) asm volatile("cp.async.wait_group 2;" ::: "memory");
        else              asm volatile("cp.async.wait_group 1;" ::: "memory");
        __syncthreads();
        if (i + NSTAGES - 1 < NITER)
            load_stage((i + NSTAGES - 1) % NSTAGES, (i + NSTAGES - 1) * 32);
        else
            asm volatile("cp.async.commit_group;" ::: "memory");

        const uint32_t stb = sb + (i % NSTAGES) * STSZ;
#pragma unroll
        for (int ks = 0; ks < 2; ks++) {
            uint32_t ah[4][4], al[4][4];
#pragma unroll
            for (int mf = 0; mf < 4; mf++) {
                int row = wm * 64 + mf * 16 + (lane & 15);
                int ch = (ks * 2 + (lane >> 4)) ^ ((row >> 1) & 3);
                uint32_t off = row * 64 + (ch << 4);
                ldsm_x4(ah[mf], stb + off);
                if (NTERMS == 3) ldsm_x4(al[mf], stb + TSZ + off);
            }
#pragma unroll
            for (int nf = 0; nf < 4; nf++) {
                uint32_t bh[2], bl[2];
                if (NTERMS == 3) {
                    int row = wn * 32 + nf * 8 + (lane & 7);
                    int ch = (ks * 2 + ((lane >> 3) & 1)) ^ ((row >> 1) & 3);
                    uint32_t off = row * 64 + (ch << 4);
                    ldsm_x2(bh, stb + 2 * TSZ + off);
                    ldsm_x2(bl, stb + 3 * TSZ + off);
                } else {
                    int row = ks * 16 + (lane & 15);
                    int ch = (wn * 4 + nf) ^ (row & 7);
                    ldsm_x2_trans(bh, stb + TSZ + row * 256 + (ch << 4));
                }
#pragma unroll
                for (int mf = 0; mf < 4; mf++) {
                    mma16816(acc[mf][nf], ah[mf], bh);
                    if (NTERMS == 3) {
                        mma16816(acc[mf][nf], ah[mf], bl);
                        mma16816(acc[mf][nf], al[mf], bh);
                    }
                }
            }
        }
    }

    float* Cb = Cout + boff;
#pragma unroll
    for (int mf = 0; mf < 4; mf++) {
#pragma unroll
        for (int nf = 0; nf < 4; nf++) {
            int r  = m0 + wm * 64 + mf * 16 + (lane >> 2);
            int cc = n0 + wn * 32 + nf * 8 + (lane & 3) * 2;
            *(float2*)&Cb[(size_t)r * S + cc]       = make_float2(acc[mf][nf][0], acc[mf][nf][1]);
            *(float2*)&Cb[(size_t)(r + 8) * S + cc] = make_float2(acc[mf][nf][2], acc[mf][nf][3]);
            if (NTERMS == 3) {
                float* Tb = CT + boff;
                Tb[(size_t)cc * S + r]           = acc[mf][nf][0];
                Tb[(size_t)(cc + 1) * S + r]     = acc[mf][nf][1];
                Tb[(size_t)cc * S + r + 8]       = acc[mf][nf][2];
                Tb[(size_t)(cc + 1) * S + r + 8] = acc[mf][nf][3];
            }
        }
    }
}

// ---------------------------------------------------------------------------
// Fused row softmax: z=0: sim rows + pre_mask -> attA [p][h]
//                    z=1: simT rows + hyp_mask -> attBT [h][p]
// One warp per row, shfl reductions. grid (S/8, NB, 2), block 256.
// ---------------------------------------------------------------------------
__global__ __launch_bounds__(256)
void softmax_fused_kernel(const int* __restrict__ pre_mask,
                          const int* __restrict__ hyp_mask,
                          __half* __restrict__ attA, __half* __restrict__ attBT)
{
    const int z = blockIdx.z;
    const float* src = z ? g_simT : g_sim;
    const int*  mask = z ? hyp_mask : pre_mask;
    __half*      dst = z ? attBT : attA;

    const int b = blockIdx.y;
    const int w = threadIdx.x >> 5, lane = threadIdx.x & 31;
    const int p = blockIdx.x * 8 + w;
    const float c = (mask[b * S + p] == 0) ? NEG_MASK : 0.0f;
    const size_t off = ((size_t)b * S + p) * S;
    const float* row = src + off;

    float4 v[4];
#pragma unroll
    for (int seg = 0; seg < 4; seg++) {
        v[seg] = *(const float4*)&row[seg * 128 + lane * 4];
        v[seg].x += c; v[seg].y += c; v[seg].z += c; v[seg].w += c;
    }

    float M = -3.0e38f;
#pragma unroll
    for (int seg = 0; seg < 4; seg++)
        M = fmaxf(M, fmaxf(fmaxf(v[seg].x, v[seg].y), fmaxf(v[seg].z, v[seg].w)));
#pragma unroll
    for (int o = 16; o > 0; o >>= 1)
        M = fmaxf(M, __shfl_xor_sync(0xFFFFFFFFu, M, o));

    float s = 0.0f;
    float4 e[4];
#pragma unroll
    for (int seg = 0; seg < 4; seg++) {
        e[seg].x = __expf(v[seg].x - M); e[seg].y = __expf(v[seg].y - M);
        e[seg].z = __expf(v[seg].z - M); e[seg].w = __expf(v[seg].w - M);
        s += e[seg].x + e[seg].y + e[seg].z + e[seg].w;
    }
#pragma unroll
    for (int o = 16; o > 0; o >>= 1)
        s += __shfl_xor_sync(0xFFFFFFFFu, s, o);
    const float inv = 1.0f / s;

#pragma unroll
    for (int seg = 0; seg < 4; seg++) {
        size_t o4 = off + seg * 128 + lane * 4;
        *(uint2*)&dst[o4] = make_uint2(
            pack2(__float2half_rn(e[seg].x * inv), __float2half_rn(e[seg].y * inv)),
            pack2(__float2half_rn(e[seg].z * inv), __float2half_rn(e[seg].w * inv)));
    }
}

// ---------------------------------------------------------------------------
extern "C" void kernel_launch(void* const* d_in, const int* in_sizes, int n_in,
                              void* d_out, int out_size)
{
    const float* premise  = (const float*)d_in[0];
    const int*   pre_mask = (const int*)  d_in[1];
    const float* hypo     = (const float*)d_in[2];
    const int*   hyp_mask = (const int*)  d_in[3];
    float* out1 = (float*)d_out;
    float* out2 = out1 + TENS;

    float *sim, *simT;
    __half* buf;
    cudaGetSymbolAddress((void**)&sim,  g_sim);
    cudaGetSymbolAddress((void**)&simT, g_simT);
    cudaGetSymbolAddress((void**)&buf,  g_buf);
    auto slot = [&](int i) { return buf + (size_t)i * TENS; };

    const int SMEM3 = 3 * 4 * 8192;   // 96 KB
    const int SMEM1 = 4 * 2 * 8192;   // 64 KB
    cudaFuncSetAttribute(gemm_tc_kernel<3>,
                         cudaFuncAttributeMaxDynamicSharedMemorySize, SMEM3);
    cudaFuncSetAttribute(gemm_tc_kernel<1>,
                         cudaFuncAttributeMaxDynamicSharedMemorySize, SMEM1);

    // 1. hi/lo fp16 splits of both inputs (element-wise, one launch)
    convert_split_kernel<<<dim3((unsigned)(TENS / 1024), 2), 256>>>(
        (const float4*)premise, (uint2*)slot(PRE_HI), (uint2*)slot(PRE_LO),
        (const float4*)hypo,    (uint2*)slot(HYP_HI), (uint2*)slot(HYP_LO));

    // 2. sim = premise @ hypothesis^T (3-term split) -> sim and simT
    gemm_tc_kernel<3><<<dim3(4, 4, NB), 256, SMEM3>>>(
        slot(PRE_HI), slot(PRE_LO), slot(HYP_HI), slot(HYP_LO), sim, simT,
        nullptr, nullptr, nullptr);

    // 3. both softmaxes in one launch -> attA [p][h], attBT [h][p]
    softmax_fused_kernel<<<dim3(S / 8, NB, 2), 256>>>(
        pre_mask, hyp_mask, slot(ATT_A), slot(ATT_BT));

    // 4+5. both attended GEMMs (B row-major via ldmatrix.trans)
    //      z<NB: attA @ hyp -> out1 ; z>=NB: attBT @ pre -> out2
    gemm_tc_kernel<1><<<dim3(4, 4, 2 * NB), 256, SMEM1>>>(
        slot(ATT_A), nullptr, slot(HYP_HI), nullptr, out1, nullptr,
        slot(ATT_BT), slot(PRE_HI), out2);
}

// round 9
// speedup vs baseline: 1.1580x; 1.0435x over previous
#include <cuda_runtime.h>
#include <cuda_fp16.h>
#include <cstdint>

#define NB 64
#define S  512
#define NEG_MASK -999999.0f

#define TENS ((size_t)NB * S * S)

// ---------------- scratch ---------------------------------------------------
__device__ float  g_sim [TENS];
__device__ float  g_simT[TENS];
__device__ __half g_buf[6 * TENS];

#define PRE_HI  0
#define PRE_LO  1
#define HYP_HI  2
#define HYP_LO  3
#define ATT_A   4
#define ATT_BT  5

// ---------------- helpers ---------------------------------------------------
__device__ __forceinline__ uint32_t smem_to_u32(const void* p) {
    uint32_t a;
    asm("{ .reg .u64 t; cvta.to.shared.u64 t, %1; cvt.u32.u64 %0, t; }" : "=r"(a) : "l"(p));
    return a;
}
__device__ __forceinline__ void ldsm_x4(uint32_t* r, uint32_t addr) {
    asm volatile("ldmatrix.sync.aligned.m8n8.x4.shared.b16 {%0,%1,%2,%3}, [%4];"
                 : "=r"(r[0]), "=r"(r[1]), "=r"(r[2]), "=r"(r[3]) : "r"(addr));
}
__device__ __forceinline__ void ldsm_x4_trans(uint32_t* r, uint32_t addr) {
    asm volatile("ldmatrix.sync.aligned.m8n8.x4.trans.shared.b16 {%0,%1,%2,%3}, [%4];"
                 : "=r"(r[0]), "=r"(r[1]), "=r"(r[2]), "=r"(r[3]) : "r"(addr));
}
__device__ __forceinline__ void mma16816(float* c, const uint32_t* a, const uint32_t* b) {
    asm volatile(
        "mma.sync.aligned.m16n8k16.row.col.f32.f16.f16.f32 "
        "{%0,%1,%2,%3}, {%4,%5,%6,%7}, {%8,%9}, {%0,%1,%2,%3};"
        : "+f"(c[0]), "+f"(c[1]), "+f"(c[2]), "+f"(c[3])
        : "r"(a[0]), "r"(a[1]), "r"(a[2]), "r"(a[3]), "r"(b[0]), "r"(b[1]));
}
__device__ __forceinline__ uint32_t pack2(__half a, __half b) {
    __half2 h = __halves2half2(a, b);
    return *reinterpret_cast<uint32_t*>(&h);
}

// ---------------------------------------------------------------------------
// Element-wise hi/lo fp16 split of both inputs. grid (TENS/1024, 2), block 256.
// ---------------------------------------------------------------------------
__global__ __launch_bounds__(256)
void convert_split_kernel(const float4* __restrict__ X1,
                          uint2* __restrict__ hi1, uint2* __restrict__ lo1,
                          const float4* __restrict__ X2,
                          uint2* __restrict__ hi2, uint2* __restrict__ lo2)
{
    const float4* X = blockIdx.y ? X2 : X1;
    uint2* hi = blockIdx.y ? hi2 : hi1;
    uint2* lo = blockIdx.y ? lo2 : lo1;
    size_t i = (size_t)blockIdx.x * 256 + threadIdx.x;
    float4 v = X[i];
    __half h0 = __float2half_rn(v.x), h1 = __float2half_rn(v.y);
    __half h2 = __float2half_rn(v.z), h3 = __float2half_rn(v.w);
    uint2 H, L;
    H.x = pack2(h0, h1);
    H.y = pack2(h2, h3);
    L.x = pack2(__float2half_rn(v.x - __half2float(h0)),
                __float2half_rn(v.y - __half2float(h1)));
    L.y = pack2(__float2half_rn(v.z - __half2float(h2)),
                __float2half_rn(v.w - __half2float(h3)));
    hi[i] = H;
    lo[i] = L;
}

// ---------------------------------------------------------------------------
// fp16 tensor-core GEMM (mma.sync m16n8k16), fp32 out.
// 128 threads = 4 warps in 2x2 grid, 64x64 warp tile (128 acc regs).
// NTERMS=3: C = Ahi*Bhi + Ahi*Blo + Alo*Bhi ; B K-major [n][k]; writes C + CT.
// NTERMS=1: C = A*B ; B row-major [k][n] via ldmatrix.x4.trans; merged dual launch.
// BK=32, multistage cp.async, 2 CTAs/SM.
// ---------------------------------------------------------------------------
template<int NTERMS>
__global__ __launch_bounds__(128, 2)
void gemm_tc_kernel(const __half* __restrict__ Ahi, const __half* __restrict__ Alo,
                    const __half* __restrict__ Bhi, const __half* __restrict__ Blo,
                    float* __restrict__ C, float* __restrict__ CT,
                    const __half* __restrict__ A2, const __half* __restrict__ B2,
                    float* __restrict__ C2)
{
    constexpr int NTILES  = (NTERMS == 3) ? 4 : 2;
    constexpr int NSTAGES = (NTERMS == 3) ? 3 : 4;
    constexpr int TSZ     = 8192;
    constexpr int STSZ    = NTILES * TSZ;
    constexpr int NITER   = 16;

    extern __shared__ char smem[];
    const uint32_t sb = smem_to_u32(smem);
    const int tid = threadIdx.x;
    const int lane = tid & 31, wid = tid >> 5;
    const int wm = wid >> 1;            // 0..1 (64 rows each)
    const int wn = wid & 1;             // 0..1 (64 cols each)
    const int zb = blockIdx.z;
    const size_t boff = (size_t)(zb & (NB - 1)) * S * S;
    const int m0 = blockIdx.y * 128, n0 = blockIdx.x * 128;

    const __half *gAhi, *gAlo, *gBhi, *gBlo, *gBkn;
    float* Cout;
    if (NTERMS == 3) {
        gAhi = Ahi + boff + (size_t)m0 * S;
        gAlo = Alo + boff + (size_t)m0 * S;
        gBhi = Bhi + boff + (size_t)n0 * S;
        gBlo = Blo + boff + (size_t)n0 * S;
        Cout = C;
    } else {
        if (zb < NB) { gAhi = Ahi + boff + (size_t)m0 * S; gBkn = Bhi + boff + n0; Cout = C; }
        else         { gAhi = A2  + boff + (size_t)m0 * S; gBkn = B2  + boff + n0; Cout = C2; }
    }

    auto load_stage = [&](int st, int k0) {
        uint32_t base = sb + st * STSZ;
        if (NTERMS == 3) {
            const __half* gs[4] = {gAhi, gAlo, gBhi, gBlo};
#pragma unroll
            for (int t = 0; t < 4; t++) {
                const __half* g = gs[t] + k0;
                uint32_t tb = base + t * TSZ;
#pragma unroll
                for (int j = 0; j < 4; j++) {
                    int idx = j * 128 + tid;
                    int row = idx >> 2, c = idx & 3;
                    uint32_t dst = tb + row * 64 + ((uint32_t)(c ^ ((row >> 1) & 3)) << 4);
                    asm volatile("cp.async.cg.shared.global [%0], [%1], 16;"
                                 :: "r"(dst), "l"(g + row * S + c * 8) : "memory");
                }
            }
        } else {
            // A tile [m128][k32], 64B rows
#pragma unroll
            for (int j = 0; j < 4; j++) {
                int idx = j * 128 + tid;
                int row = idx >> 2, c = idx & 3;
                uint32_t dst = base + row * 64 + ((uint32_t)(c ^ ((row >> 1) & 3)) << 4);
                asm volatile("cp.async.cg.shared.global [%0], [%1], 16;"
                             :: "r"(dst), "l"(gAhi + row * S + k0 + c * 8) : "memory");
            }
            // B tile [k32][n128], 256B rows, row-XOR swizzle
#pragma unroll
            for (int j = 0; j < 4; j++) {
                int idx = j * 128 + tid;
                int row = idx >> 4, c = idx & 15;
                uint32_t dst = base + TSZ + row * 256 + ((uint32_t)(c ^ (row & 7)) << 4);
                asm volatile("cp.async.cg.shared.global [%0], [%1], 16;"
                             :: "r"(dst), "l"(gBkn + (size_t)(k0 + row) * S + c * 8) : "memory");
            }
        }
        asm volatile("cp.async.commit_group;" ::: "memory");
    };

    float acc[4][8][4];
#pragma unroll
    for (int i = 0; i < 4; i++)
#pragma unroll
        for (int j = 0; j < 8; j++)
#pragma unroll
            for (int q = 0; q < 4; q++) acc[i][j][q] = 0.0f;

#pragma unroll
    for (int s = 0; s < NSTAGES - 1; s++) load_stage(s, s * 32);

    for (int i = 0; i < NITER; i++) {
        if (NSTAGES == 4) asm volatile("cp.async.wait_group 2;" ::: "memory");
        else              asm volatile("cp.async.wait_group 1;" ::: "memory");
        __syncthreads();
        if (i + NSTAGES - 1 < NITER)
            load_stage((i + NSTAGES - 1) % NSTAGES, (i + NSTAGES - 1) * 32);
        else
            asm volatile("cp.async.commit_group;" ::: "memory");

        const uint32_t stb = sb + (i % NSTAGES) * STSZ;
#pragma unroll
        for (int ks = 0; ks < 2; ks++) {
            uint32_t ah[4][4], al[4][4];
#pragma unroll
            for (int mf = 0; mf < 4; mf++) {
                int row = wm * 64 + mf * 16 + (lane & 15);
                int ch = (ks * 2 + (lane >> 4)) ^ ((row >> 1) & 3);
                uint32_t off = row * 64 + (ch << 4);
                ldsm_x4(ah[mf], stb + off);
                if (NTERMS == 3) ldsm_x4(al[mf], stb + TSZ + off);
            }
#pragma unroll
            for (int nfp = 0; nfp < 4; nfp++) {      // pairs of n8 groups
                uint32_t bh[4], bl[4];
                if (NTERMS == 3) {
                    // B K-major [n][k], 64B rows: x4 = 2 n-groups x 2 k-chunks
                    int nrow = wn * 64 + nfp * 16 + ((lane >> 4) << 3) + (lane & 7);
                    int ch = (ks * 2 + ((lane >> 3) & 1)) ^ ((nrow >> 1) & 3);
                    uint32_t off = nrow * 64 + (ch << 4);
                    ldsm_x4(bh, stb + 2 * TSZ + off);
                    ldsm_x4(bl, stb + 3 * TSZ + off);
                } else {
                    // B row-major [k][n], 256B rows: x4.trans = 2 n-groups
                    int row = ks * 16 + ((lane >> 3) & 1) * 8 + (lane & 7);
                    int chunk = wn * 8 + nfp * 2 + (lane >> 4);
                    uint32_t off = row * 256 + ((uint32_t)(chunk ^ (row & 7)) << 4);
                    ldsm_x4_trans(bh, stb + TSZ + off);
                }
#pragma unroll
                for (int nn = 0; nn < 2; nn++) {
                    int nf = nfp * 2 + nn;
#pragma unroll
                    for (int mf = 0; mf < 4; mf++) {
                        mma16816(acc[mf][nf], ah[mf], bh + nn * 2);
                        if (NTERMS == 3) {
                            mma16816(acc[mf][nf], ah[mf], bl + nn * 2);
                            mma16816(acc[mf][nf], al[mf], bh + nn * 2);
                        }
                    }
                }
            }
        }
    }

    float* Cb = Cout + boff;
#pragma unroll
    for (int mf = 0; mf < 4; mf++) {
#pragma unroll
        for (int nf = 0; nf < 8; nf++) {
            int r  = m0 + wm * 64 + mf * 16 + (lane >> 2);
            int cc = n0 + wn * 64 + nf * 8 + (lane & 3) * 2;
            *(float2*)&Cb[(size_t)r * S + cc]       = make_float2(acc[mf][nf][0], acc[mf][nf][1]);
            *(float2*)&Cb[(size_t)(r + 8) * S + cc] = make_float2(acc[mf][nf][2], acc[mf][nf][3]);
            if (NTERMS == 3) {
                float* Tb = CT + boff;
                Tb[(size_t)cc * S + r]           = acc[mf][nf][0];
                Tb[(size_t)(cc + 1) * S + r]     = acc[mf][nf][1];
                Tb[(size_t)cc * S + r + 8]       = acc[mf][nf][2];
                Tb[(size_t)(cc + 1) * S + r + 8] = acc[mf][nf][3];
            }
        }
    }
}

// ---------------------------------------------------------------------------
// Fused row softmax: z=0: sim rows + pre_mask -> attA [p][h]
//                    z=1: simT rows + hyp_mask -> attBT [h][p]
// One warp per row, shfl reductions. grid (S/8, NB, 2), block 256.
// ---------------------------------------------------------------------------
__global__ __launch_bounds__(256)
void softmax_fused_kernel(const int* __restrict__ pre_mask,
                          const int* __restrict__ hyp_mask,
                          __half* __restrict__ attA, __half* __restrict__ attBT)
{
    const int z = blockIdx.z;
    const float* src = z ? g_simT : g_sim;
    const int*  mask = z ? hyp_mask : pre_mask;
    __half*      dst = z ? attBT : attA;

    const int b = blockIdx.y;
    const int w = threadIdx.x >> 5, lane = threadIdx.x & 31;
    const int p = blockIdx.x * 8 + w;
    const float c = (mask[b * S + p] == 0) ? NEG_MASK : 0.0f;
    const size_t off = ((size_t)b * S + p) * S;
    const float* row = src + off;

    float4 v[4];
#pragma unroll
    for (int seg = 0; seg < 4; seg++) {
        v[seg] = *(const float4*)&row[seg * 128 + lane * 4];
        v[seg].x += c; v[seg].y += c; v[seg].z += c; v[seg].w += c;
    }

    float M = -3.0e38f;
#pragma unroll
    for (int seg = 0; seg < 4; seg++)
        M = fmaxf(M, fmaxf(fmaxf(v[seg].x, v[seg].y), fmaxf(v[seg].z, v[seg].w)));
#pragma unroll
    for (int o = 16; o > 0; o >>= 1)
        M = fmaxf(M, __shfl_xor_sync(0xFFFFFFFFu, M, o));

    float s = 0.0f;
    float4 e[4];
#pragma unroll
    for (int seg = 0; seg < 4; seg++) {
        e[seg].x = __expf(v[seg].x - M); e[seg].y = __expf(v[seg].y - M);
        e[seg].z = __expf(v[seg].z - M); e[seg].w = __expf(v[seg].w - M);
        s += e[seg].x + e[seg].y + e[seg].z + e[seg].w;
    }
#pragma unroll
    for (int o = 16; o > 0; o >>= 1)
        s += __shfl_xor_sync(0xFFFFFFFFu, s, o);
    const float inv = 1.0f / s;

#pragma unroll
    for (int seg = 0; seg < 4; seg++) {
        size_t o4 = off + seg * 128 + lane * 4;
        *(uint2*)&dst[o4] = make_uint2(
            pack2(__float2half_rn(e[seg].x * inv), __float2half_rn(e[seg].y * inv)),
            pack2(__float2half_rn(e[seg].z * inv), __float2half_rn(e[seg].w * inv)));
    }
}

// ---------------------------------------------------------------------------
extern "C" void kernel_launch(void* const* d_in, const int* in_sizes, int n_in,
                              void* d_out, int out_size)
{
    const float* premise  = (const float*)d_in[0];
    const int*   pre_mask = (const int*)  d_in[1];
    const float* hypo     = (const float*)d_in[2];
    const int*   hyp_mask = (const int*)  d_in[3];
    float* out1 = (float*)d_out;
    float* out2 = out1 + TENS;

    float *sim, *simT;
    __half* buf;
    cudaGetSymbolAddress((void**)&sim,  g_sim);
    cudaGetSymbolAddress((void**)&simT, g_simT);
    cudaGetSymbolAddress((void**)&buf,  g_buf);
    auto slot = [&](int i) { return buf + (size_t)i * TENS; };

    const int SMEM3 = 3 * 4 * 8192;   // 96 KB
    const int SMEM1 = 4 * 2 * 8192;   // 64 KB
    cudaFuncSetAttribute(gemm_tc_kernel<3>,
                         cudaFuncAttributeMaxDynamicSharedMemorySize, SMEM3);
    cudaFuncSetAttribute(gemm_tc_kernel<1>,
                         cudaFuncAttributeMaxDynamicSharedMemorySize, SMEM1);

    // 1. hi/lo fp16 splits of both inputs (element-wise, one launch)
    convert_split_kernel<<<dim3((unsigned)(TENS / 1024), 2), 256>>>(
        (const float4*)premise, (uint2*)slot(PRE_HI), (uint2*)slot(PRE_LO),
        (const float4*)hypo,    (uint2*)slot(HYP_HI), (uint2*)slot(HYP_LO));

    // 2. sim = premise @ hypothesis^T (3-term split) -> sim and simT
    gemm_tc_kernel<3><<<dim3(4, 4, NB), 128, SMEM3>>>(
        slot(PRE_HI), slot(PRE_LO), slot(HYP_HI), slot(HYP_LO), sim, simT,
        nullptr, nullptr, nullptr);

    // 3. both softmaxes in one launch -> attA [p][h], attBT [h][p]
    softmax_fused_kernel<<<dim3(S / 8, NB, 2), 256>>>(
        pre_mask, hyp_mask, slot(ATT_A), slot(ATT_BT));

    // 4+5. both attended GEMMs (B row-major via ldmatrix.x4.trans)
    //      z<NB: attA @ hyp -> out1 ; z>=NB: attBT @ pre -> out2
    gemm_tc_kernel<1><<<dim3(4, 4, 2 * NB), 128, SMEM1>>>(
        slot(ATT_A), nullptr, slot(HYP_HI), nullptr, out1, nullptr,
        slot(ATT_BT), slot(PRE_HI), out2);
}